// round 14
// baseline (speedup 1.0000x reference)
#include <cuda_runtime.h>
#include <cstdint>
#include <math.h>

// Problem dims
#define T_TOKENS 2048
#define HDIM     3584
#define IDIM     18944
#define WELEMS   ((long long)IDIM * HDIM)

// ---------------------------------------------------------------------------
// Scratch (device globals)
// ---------------------------------------------------------------------------
__device__ __align__(16) int8_t g_qx[(size_t)T_TOKENS * HDIM];
__device__ float               g_sx[T_TOKENS];
__device__ __align__(16) int8_t g_qh[(size_t)T_TOKENS * IDIM];
__device__ __align__(16) int8_t g_w8g[WELEMS];
__device__ __align__(16) int8_t g_w8u[WELEMS];
__device__ __align__(16) int8_t g_w8d[WELEMS];
__device__ int g_is32[3];

// ---------------------------------------------------------------------------
// Helpers
// ---------------------------------------------------------------------------
__device__ __forceinline__ uint32_t smem_u32(const void* p) {
    return (uint32_t)__cvta_generic_to_shared(p);
}
__device__ __forceinline__ void cp16(uint32_t dst, const void* src) {
    asm volatile("cp.async.cg.shared.global [%0], [%1], 16;" :: "r"(dst), "l"(src));
}
__device__ __forceinline__ void cp_commit() {
    asm volatile("cp.async.commit_group;");
}
template <int N>
__device__ __forceinline__ void cp_wait() {
    asm volatile("cp.async.wait_group %0;" :: "n"(N));
}
__device__ __forceinline__ void ldsm_x4(uint32_t* r, uint32_t saddr) {
    asm volatile("ldmatrix.sync.aligned.m8n8.x4.shared.b16 {%0,%1,%2,%3}, [%4];"
                 : "=r"(r[0]), "=r"(r[1]), "=r"(r[2]), "=r"(r[3]) : "r"(saddr));
}
__device__ __forceinline__ void mma_s8(int* c, const uint32_t* a, uint32_t b0, uint32_t b1) {
    asm volatile(
        "mma.sync.aligned.m16n8k32.row.col.s32.s8.s8.s32 "
        "{%0,%1,%2,%3},{%4,%5,%6,%7},{%8,%9},{%0,%1,%2,%3};"
        : "+r"(c[0]), "+r"(c[1]), "+r"(c[2]), "+r"(c[3])
        : "r"(a[0]), "r"(a[1]), "r"(a[2]), "r"(a[3]), "r"(b0), "r"(b1));
}
__device__ __forceinline__ signed char qsilu(int gi, int ui, float srow,
                                             float gs, float us, float dis) {
    float gv = (float)gi * srow * gs;
    float uv = (float)ui * srow * us;
    float h  = (gv / (1.0f + expf(-gv))) * uv;
    float q  = rintf(h / dis);
    q = fminf(fmaxf(q, -127.0f), 127.0f);
    return (signed char)(int)q;
}
__device__ __forceinline__ void dp4x4(int& acc, const int4& a, const int4& b) {
    acc = __dp4a(a.x, b.x, acc);
    acc = __dp4a(a.y, b.y, acc);
    acc = __dp4a(a.z, b.z, acc);
    acc = __dp4a(a.w, b.w, acc);
}

constexpr int SSTR = 144;     // 128B row + 16B pad (16B-aligned, conflict-free)
// fc1: 3 stages x (A 18432 | G 18432 | U 18432)
#define FC1_STG   55296
#define FC1_SMEM  (3 * FC1_STG)    // 165888, 1 CTA/SM
// fc2 (R9 exact): 3 stages x (A 18432 | B 18432)
#define FC2_STG   36864
#define FC2_SMEM  (3 * FC2_STG)    // 110592

// ---------------------------------------------------------------------------
// Dtype detector + fused repack (R9-proven)
// ---------------------------------------------------------------------------
__global__ void detect_kernel(const void* w0, const void* w1, const void* w2) {
    if (threadIdx.x == 0 && blockIdx.x == 0) {
        const void* ws[3] = {w0, w1, w2};
        for (int j = 0; j < 3; j++) {
            const int* p = (const int*)ws[j];
            int ok = 1;
            for (int i = 0; i < 16; i++) {
                int v = p[i];
                if (v < -127 || v > 127) ok = 0;
            }
            g_is32[j] = ok;
        }
    }
}

__global__ __launch_bounds__(256) void repack_all_kernel(
    const void* __restrict__ w0, const void* __restrict__ w1,
    const void* __restrict__ w2,
    int8_t* __restrict__ d0, int8_t* __restrict__ d1, int8_t* __restrict__ d2)
{
    const int which = blockIdx.y;
    const void* src = (which == 0) ? w0 : (which == 1) ? w1 : w2;
    int8_t*     dst = (which == 0) ? d0 : (which == 1) ? d1 : d2;

    const long long i = ((long long)blockIdx.x * blockDim.x + threadIdx.x) * 4;
    if (i >= WELEMS) return;
    if (g_is32[which]) {
        const int4 v = ((const int4*)src)[i >> 2];
        char4 c;
        c.x = (signed char)v.x; c.y = (signed char)v.y;
        c.z = (signed char)v.z; c.w = (signed char)v.w;
        *(char4*)(dst + i) = c;
    } else {
        *(char4*)(dst + i) = ((const char4*)src)[i >> 2];
    }
}

// ---------------------------------------------------------------------------
// Kernel 0: per-token dynamic int8 quantization of x
// ---------------------------------------------------------------------------
__global__ __launch_bounds__(256) void quant_x_kernel(const float* __restrict__ x) {
    const int row = blockIdx.x;
    const float4* xr = (const float4*)(x + (size_t)row * HDIM);
    const int nv = HDIM / 4;

    float m = 0.0f;
    for (int i = threadIdx.x; i < nv; i += blockDim.x) {
        float4 v = xr[i];
        m = fmaxf(m, fmaxf(fmaxf(fabsf(v.x), fabsf(v.y)), fmaxf(fabsf(v.z), fabsf(v.w))));
    }
    __shared__ float red[32];
    #pragma unroll
    for (int o = 16; o; o >>= 1) m = fmaxf(m, __shfl_xor_sync(0xFFFFFFFFu, m, o));
    if ((threadIdx.x & 31) == 0) red[threadIdx.x >> 5] = m;
    __syncthreads();
    if (threadIdx.x < 32) {
        float v = (threadIdx.x < (blockDim.x >> 5)) ? red[threadIdx.x] : 0.0f;
        #pragma unroll
        for (int o = 16; o; o >>= 1) v = fmaxf(v, __shfl_xor_sync(0xFFFFFFFFu, v, o));
        if (threadIdx.x == 0) red[0] = v;
    }
    __syncthreads();
    const float s = fmaxf(red[0] / 127.0f, 1e-8f);
    if (threadIdx.x == 0) g_sx[row] = s;

    char4* qr = (char4*)(g_qx + (size_t)row * HDIM);
    for (int i = threadIdx.x; i < nv; i += blockDim.x) {
        float4 v = xr[i];
        char4 q;
        q.x = (signed char)(int)fminf(fmaxf(rintf(v.x / s), -127.0f), 127.0f);
        q.y = (signed char)(int)fminf(fmaxf(rintf(v.y / s), -127.0f), 127.0f);
        q.z = (signed char)(int)fminf(fmaxf(rintf(v.z / s), -127.0f), 127.0f);
        q.w = (signed char)(int)fminf(fmaxf(rintf(v.w / s), -127.0f), 127.0f);
        qr[i] = q;
    }
}

// ---------------------------------------------------------------------------
// fc1 HYBRID dense: 768 threads, BM=128, BN=128, BK=128, 3-stage ring.
//   warps 0-15 : IMMA on cols [n0, n0+64), 4 warps/SMSP, warp tile 32r x 16c
//   warps 16-23: dp4a on cols [n0+64, n0+128), R9 layout, i-blocked operands
// ---------------------------------------------------------------------------
__global__ __launch_bounds__(768, 1) void fc1_kernel(
    const float* __restrict__ gsp, const float* __restrict__ usp,
    const float* __restrict__ disp)
{
    extern __shared__ __align__(128) int8_t smem[];
    const uint32_t sb = smem_u32(smem);

    const int tid = threadIdx.x;
    const int m0 = blockIdx.x * 128;   // M fastest -> weight L2 reuse
    const int n0 = blockIdx.y * 128;

    auto load_stage = [&](int s) {
        const uint32_t base = sb + (uint32_t)(s % 3) * FC1_STG;
        const int kb = s * 128;
        // 3 x 1024 chunks = 3072... A:1024, G:1024, U:1024 -> 1 chunk each per
        // thread covers 768; remaining 256 each by first 256 threads.
        {
            const int r = tid >> 3, c = (tid & 7) * 16;          // tid<1024 rows 0..95
            // A rows 0..95 by all 768 threads:
            cp16(base + r * SSTR + c, g_qx + (size_t)(m0 + r) * HDIM + kb + c);
            cp16(base + 18432 + r * SSTR + c, g_w8g + (size_t)(n0 + r) * HDIM + kb + c);
            cp16(base + 36864 + r * SSTR + c, g_w8u + (size_t)(n0 + r) * HDIM + kb + c);
        }
        if (tid < 256) {
            const int idx = tid + 768;
            const int r = idx >> 3, c = (idx & 7) * 16;          // rows 96..127
            cp16(base + r * SSTR + c, g_qx + (size_t)(m0 + r) * HDIM + kb + c);
            cp16(base + 18432 + r * SSTR + c, g_w8g + (size_t)(n0 + r) * HDIM + kb + c);
            cp16(base + 36864 + r * SSTR + c, g_w8u + (size_t)(n0 + r) * HDIM + kb + c);
        }
    };

    const int S = HDIM / 128;  // 28
    load_stage(0); cp_commit();
    load_stage(1); cp_commit();

    if (tid < 512) {
        // ============ IMMA half: 16 warps, warp tile 32 rows x 16 cols ======
        const int warp = tid >> 5, lane = tid & 31;
        const int wm = warp >> 2, wn = warp & 3;   // 4m x 4n
        const int g  = lane >> 2, tg = lane & 3;
        const uint32_t aoff = (uint32_t)(((lane & 7) + ((lane >> 3) & 1) * 8) * SSTR + (lane >> 4) * 16);
        const uint32_t boff = (uint32_t)(((lane & 7) + (lane >> 4) * 8) * SSTR + ((lane >> 3) & 1) * 16);

        int accG[2][2][4] = {};
        int accU[2][2][4] = {};

        for (int s = 0; s < S; s++) {
            cp_wait<1>();
            __syncthreads();
            if (s + 2 < S) load_stage(s + 2);
            cp_commit();

            const uint32_t base = sb + (uint32_t)(s % 3) * FC1_STG;
            const uint32_t abase = base + (uint32_t)(wm * 32) * SSTR + aoff;
            const uint32_t gbase = base + 18432 + (uint32_t)(wn * 16) * SSTR + boff;
            const uint32_t ubase = base + 36864 + (uint32_t)(wn * 16) * SSTR + boff;

            #pragma unroll
            for (int ks = 0; ks < 4; ks++) {
                uint32_t a[2][4];
                ldsm_x4(a[0], abase + ks * 32);
                ldsm_x4(a[1], abase + 16 * SSTR + ks * 32);
                uint32_t bg[4], bu[4];
                ldsm_x4(bg, gbase + ks * 32);
                ldsm_x4(bu, ubase + ks * 32);
                #pragma unroll
                for (int mt = 0; mt < 2; mt++) {
                    mma_s8(accG[mt][0], a[mt], bg[0], bg[1]);
                    mma_s8(accG[mt][1], a[mt], bg[2], bg[3]);
                    mma_s8(accU[mt][0], a[mt], bu[0], bu[1]);
                    mma_s8(accU[mt][1], a[mt], bu[2], bu[3]);
                }
            }
        }

        const float gscale = *gsp, uscale = *usp, dis = *disp;
        #pragma unroll
        for (int mt = 0; mt < 2; mt++) {
            const int r0 = m0 + wm * 32 + mt * 16 + g;
            const float s0 = g_sx[r0], s1 = g_sx[r0 + 8];
            #pragma unroll
            for (int nt = 0; nt < 2; nt++) {
                const int c = n0 + wn * 16 + nt * 8 + tg * 2;
                char2 v0, v1;
                v0.x = qsilu(accG[mt][nt][0], accU[mt][nt][0], s0, gscale, uscale, dis);
                v0.y = qsilu(accG[mt][nt][1], accU[mt][nt][1], s0, gscale, uscale, dis);
                v1.x = qsilu(accG[mt][nt][2], accU[mt][nt][2], s1, gscale, uscale, dis);
                v1.y = qsilu(accG[mt][nt][3], accU[mt][nt][3], s1, gscale, uscale, dis);
                *(char2*)&g_qh[(size_t)r0 * IDIM + c]       = v0;
                *(char2*)&g_qh[(size_t)(r0 + 8) * IDIM + c] = v1;
            }
        }
    } else {
        // ============ dp4a half: 8 warps, R9 layout, i-blocked ==============
        const int wt = tid - 512;
        const int ty = wt >> 4, tx = wt & 15;

        int ag[8][4] = {};
        int au[8][4] = {};

        for (int s = 0; s < S; s++) {
            cp_wait<1>();
            __syncthreads();
            if (s + 2 < S) load_stage(s + 2);
            cp_commit();

            const int so = (s % 3) * FC1_STG;
            const int8_t* Ab = smem + so + ty * 8 * SSTR;
            const int8_t* Gb = smem + so + 18432 + (64 + tx) * SSTR;
            const int8_t* Ub = smem + so + 36864 + (64 + tx) * SSTR;

            #pragma unroll
            for (int k4 = 0; k4 < 8; k4++) {
                #pragma unroll
                for (int ib = 0; ib < 2; ib++) {
                    int4 a4[4];
                    #pragma unroll
                    for (int i = 0; i < 4; i++)
                        a4[i] = *(const int4*)(Ab + (ib * 4 + i) * SSTR + k4 * 16);
                    #pragma unroll
                    for (int j = 0; j < 4; j++) {
                        const int4 bg4 = *(const int4*)(Gb + j * 16 * SSTR + k4 * 16);
                        const int4 bu4 = *(const int4*)(Ub + j * 16 * SSTR + k4 * 16);
                        #pragma unroll
                        for (int i = 0; i < 4; i++) {
                            dp4x4(ag[ib * 4 + i][j], a4[i], bg4);
                            dp4x4(au[ib * 4 + i][j], a4[i], bu4);
                        }
                    }
                }
            }
        }

        const float gscale = *gsp, uscale = *usp, dis = *disp;
        #pragma unroll
        for (int i = 0; i < 8; i++) {
            const int row = m0 + ty * 8 + i;
            const float srow = g_sx[row];
            #pragma unroll
            for (int j = 0; j < 4; j++) {
                const int col = n0 + 64 + tx + 16 * j;
                g_qh[(size_t)row * IDIM + col] =
                    qsilu(ag[i][j], au[i][j], srow, gscale, uscale, dis);
            }
        }
    }
}

// ---------------------------------------------------------------------------
// fc2 HYBRID (R9 exact): 512 threads, BM=128, BN=128, BK=128, 3-stage ring.
// ---------------------------------------------------------------------------
__global__ __launch_bounds__(512, 1) void fc2_kernel(
    const float* __restrict__ dsp, const float* __restrict__ disp,
    float* __restrict__ out)
{
    extern __shared__ __align__(128) int8_t smem[];
    const uint32_t sb = smem_u32(smem);

    const int tid = threadIdx.x;
    const int m0 = blockIdx.x * 128;
    const int n0 = blockIdx.y * 128;

    auto load_stage = [&](int s) {
        const uint32_t base = sb + (uint32_t)(s % 3) * FC2_STG;
        const int kb = s * 128;
        #pragma unroll
        for (int i = 0; i < 2; i++) {
            const int idx = tid + i * 512;
            const int r = idx >> 3, c = (idx & 7) * 16;
            cp16(base + r * SSTR + c,         g_qh  + (size_t)(m0 + r) * IDIM + kb + c);
            cp16(base + 18432 + r * SSTR + c, g_w8d + (size_t)(n0 + r) * IDIM + kb + c);
        }
    };

    const int S = IDIM / 128;  // 148
    load_stage(0); cp_commit();
    load_stage(1); cp_commit();

    if (tid < 256) {
        // ===================== IMMA half =====================
        const int warp = tid >> 5, lane = tid & 31;
        const int wm = warp >> 1, wn = warp & 1;
        const int g  = lane >> 2, tg = lane & 3;
        const uint32_t aoff = (uint32_t)(((lane & 7) + ((lane >> 3) & 1) * 8) * SSTR + (lane >> 4) * 16);
        const uint32_t boff = (uint32_t)(((lane & 7) + (lane >> 4) * 8) * SSTR + ((lane >> 3) & 1) * 16);

        int acc[2][4][4] = {};

        for (int s = 0; s < S; s++) {
            cp_wait<1>();
            __syncthreads();
            if (s + 2 < S) load_stage(s + 2);
            cp_commit();

            const uint32_t base = sb + (uint32_t)(s % 3) * FC2_STG;
            const uint32_t abase = base + (uint32_t)(wm * 32) * SSTR + aoff;
            const uint32_t bbase = base + 18432 + (uint32_t)(wn * 32) * SSTR + boff;

            #pragma unroll
            for (int ks = 0; ks < 4; ks++) {
                uint32_t a[2][4];
                ldsm_x4(a[0], abase + ks * 32);
                ldsm_x4(a[1], abase + 16 * SSTR + ks * 32);
                #pragma unroll
                for (int p = 0; p < 2; p++) {
                    uint32_t bb[4];
                    ldsm_x4(bb, bbase + p * 16 * SSTR + ks * 32);
                    #pragma unroll
                    for (int mt = 0; mt < 2; mt++) {
                        mma_s8(acc[mt][2 * p],     a[mt], bb[0], bb[1]);
                        mma_s8(acc[mt][2 * p + 1], a[mt], bb[2], bb[3]);
                    }
                }
            }
        }

        const float oscale = (*disp) * (*dsp);
        #pragma unroll
        for (int mt = 0; mt < 2; mt++) {
            const int r0 = m0 + wm * 32 + mt * 16 + g;
            #pragma unroll
            for (int nt = 0; nt < 4; nt++) {
                const int c = n0 + wn * 32 + nt * 8 + tg * 2;
                float2 v0, v1;
                v0.x = (float)acc[mt][nt][0] * oscale;
                v0.y = (float)acc[mt][nt][1] * oscale;
                v1.x = (float)acc[mt][nt][2] * oscale;
                v1.y = (float)acc[mt][nt][3] * oscale;
                *(float2*)&out[(size_t)r0 * HDIM + c]       = v0;
                *(float2*)&out[(size_t)(r0 + 8) * HDIM + c] = v1;
            }
        }
    } else {
        // ===================== dp4a half =====================
        const int wt = tid - 256;
        const int ty = wt >> 4, tx = wt & 15;

        int acc[8][4] = {};

        for (int s = 0; s < S; s++) {
            cp_wait<1>();
            __syncthreads();
            if (s + 2 < S) load_stage(s + 2);
            cp_commit();

            const int so = (s % 3) * FC2_STG;
            const int8_t* Ab = smem + so + ty * 8 * SSTR;
            const int8_t* Bb = smem + so + 18432 + (64 + tx) * SSTR;

            #pragma unroll
            for (int k4 = 0; k4 < 8; k4++) {
                int4 a4[8];
                #pragma unroll
                for (int i = 0; i < 8; i++)
                    a4[i] = *(const int4*)(Ab + i * SSTR + k4 * 16);
                #pragma unroll
                for (int j = 0; j < 4; j++) {
                    const int4 b4 = *(const int4*)(Bb + j * 16 * SSTR + k4 * 16);
                    #pragma unroll
                    for (int i = 0; i < 8; i++)
                        dp4x4(acc[i][j], a4[i], b4);
                }
            }
        }

        const float oscale = (*disp) * (*dsp);
        #pragma unroll
        for (int i = 0; i < 8; i++) {
            const int row = m0 + ty * 8 + i;
            #pragma unroll
            for (int j = 0; j < 4; j++) {
                const int col = n0 + 64 + tx + 16 * j;
                out[(size_t)row * HDIM + col] = (float)acc[i][j] * oscale;
            }
        }
    }
}

// ---------------------------------------------------------------------------
// Entry point
// ---------------------------------------------------------------------------
extern "C" void kernel_launch(void* const* d_in, const int* in_sizes, int n_in,
                              void* d_out, int out_size) {
    const int XSZ = T_TOKENS * HDIM;

    int xi = -1, widx[3] = {-1,-1,-1}, sidx[4] = {-1,-1,-1,-1};
    int nw = 0, ns = 0;
    for (int i = 0; i < n_in; i++) {
        if (in_sizes[i] == XSZ) xi = i;
        else if ((long long)in_sizes[i] == WELEMS) { if (nw < 3) widx[nw++] = i; }
        else if (in_sizes[i] == 1) { if (ns < 4) sidx[ns++] = i; }
    }

    const float *x, *gs, *us, *ds, *dis;
    const void *gw, *uw, *dw;

    if (xi == 0) {
        x   = (const float*)d_in[xi];
        gw  = d_in[widx[0]];
        uw  = d_in[widx[1]];
        dw  = d_in[widx[2]];
        gs  = (const float*)d_in[sidx[0]];
        us  = (const float*)d_in[sidx[1]];
        ds  = (const float*)d_in[sidx[2]];
        dis = (const float*)d_in[sidx[3]];
    } else {
        x   = (const float*)d_in[xi];
        dw  = d_in[widx[0]];
        gw  = d_in[widx[1]];
        uw  = d_in[widx[2]];
        dis = (const float*)d_in[sidx[0]];
        ds  = (const float*)d_in[sidx[1]];
        gs  = (const float*)d_in[sidx[2]];
        us  = (const float*)d_in[sidx[3]];
    }

    float* out = (float*)d_out;

    static int smem_set = 0;
    if (!smem_set) {
        cudaFuncSetAttribute(fc1_kernel, cudaFuncAttributeMaxDynamicSharedMemorySize, FC1_SMEM);
        cudaFuncSetAttribute(fc2_kernel, cudaFuncAttributeMaxDynamicSharedMemorySize, FC2_SMEM);
        smem_set = 1;
    }

    detect_kernel<<<1, 32>>>(gw, uw, dw);

    int8_t* w8g; cudaGetSymbolAddress((void**)&w8g, g_w8g);
    int8_t* w8u; cudaGetSymbolAddress((void**)&w8u, g_w8u);
    int8_t* w8d; cudaGetSymbolAddress((void**)&w8d, g_w8d);
    const int rp_blocks = (int)((WELEMS / 4 + 255) / 256);
    repack_all_kernel<<<dim3(rp_blocks, 3), 256>>>(gw, uw, dw, w8g, w8u, w8d);

    quant_x_kernel<<<T_TOKENS, 256>>>(x);

    // M fastest (grid.x) so concurrent CTAs share weight stripes in L2.
    fc1_kernel<<<dim3(T_TOKENS / 128, IDIM / 128), 768, FC1_SMEM>>>(gs, us, dis);
    fc2_kernel<<<dim3(T_TOKENS / 128, HDIM / 128), 512, FC2_SMEM>>>(ds, dis, out);
}

// round 15
// speedup vs baseline: 1.3494x; 1.3494x over previous
#include <cuda_runtime.h>
#include <cstdint>
#include <math.h>

// Problem dims
#define T_TOKENS 2048
#define HDIM     3584
#define IDIM     18944
#define WELEMS   ((long long)IDIM * HDIM)

// ---------------------------------------------------------------------------
// Scratch (device globals)
// ---------------------------------------------------------------------------
__device__ __align__(16) int8_t g_qx[(size_t)T_TOKENS * HDIM];
__device__ float               g_sx[T_TOKENS];
__device__ __align__(16) int8_t g_qh[(size_t)T_TOKENS * IDIM];
__device__ __align__(16) int8_t g_w8g[WELEMS];
__device__ __align__(16) int8_t g_w8u[WELEMS];
__device__ __align__(16) int8_t g_w8d[WELEMS];
__device__ int g_is32[3];

// ---------------------------------------------------------------------------
// Helpers
// ---------------------------------------------------------------------------
__device__ __forceinline__ uint32_t smem_u32(const void* p) {
    return (uint32_t)__cvta_generic_to_shared(p);
}
__device__ __forceinline__ void cp16(uint32_t dst, const void* src) {
    asm volatile("cp.async.cg.shared.global [%0], [%1], 16;" :: "r"(dst), "l"(src));
}
__device__ __forceinline__ void cp_commit() {
    asm volatile("cp.async.commit_group;");
}
template <int N>
__device__ __forceinline__ void cp_wait() {
    asm volatile("cp.async.wait_group %0;" :: "n"(N));
}
__device__ __forceinline__ void ldsm_x4(uint32_t* r, uint32_t saddr) {
    asm volatile("ldmatrix.sync.aligned.m8n8.x4.shared.b16 {%0,%1,%2,%3}, [%4];"
                 : "=r"(r[0]), "=r"(r[1]), "=r"(r[2]), "=r"(r[3]) : "r"(saddr));
}
__device__ __forceinline__ void mma_s8(int* c, const uint32_t* a, uint32_t b0, uint32_t b1) {
    asm volatile(
        "mma.sync.aligned.m16n8k32.row.col.s32.s8.s8.s32 "
        "{%0,%1,%2,%3},{%4,%5,%6,%7},{%8,%9},{%0,%1,%2,%3};"
        : "+r"(c[0]), "+r"(c[1]), "+r"(c[2]), "+r"(c[3])
        : "r"(a[0]), "r"(a[1]), "r"(a[2]), "r"(a[3]), "r"(b0), "r"(b1));
}
__device__ __forceinline__ signed char qsilu(int gi, int ui, float srow,
                                             float gs, float us, float dis) {
    float gv = (float)gi * srow * gs;
    float uv = (float)ui * srow * us;
    float h  = (gv / (1.0f + expf(-gv))) * uv;
    float q  = rintf(h / dis);
    q = fminf(fmaxf(q, -127.0f), 127.0f);
    return (signed char)(int)q;
}
__device__ __forceinline__ void dp4x4(int& acc, const int4& a, const int4& b) {
    acc = __dp4a(a.x, b.x, acc);
    acc = __dp4a(a.y, b.y, acc);
    acc = __dp4a(a.z, b.z, acc);
    acc = __dp4a(a.w, b.w, acc);
}

constexpr int SSTR = 144;     // 128B row + 16B pad (16B-aligned, conflict-free)
// fc1: 3 stages x (A 18432 | G 18432 | U 18432)
#define FC1_STG   55296
#define FC1_SMEM  (3 * FC1_STG)    // 165888, 1 CTA/SM
// fc2 (R9 exact): 3 stages x (A 18432 | B 18432)
#define FC2_STG   36864
#define FC2_SMEM  (3 * FC2_STG)    // 110592

// ---------------------------------------------------------------------------
// Dtype detector + fused repack (R9-proven)
// ---------------------------------------------------------------------------
__global__ void detect_kernel(const void* w0, const void* w1, const void* w2) {
    if (threadIdx.x == 0 && blockIdx.x == 0) {
        const void* ws[3] = {w0, w1, w2};
        for (int j = 0; j < 3; j++) {
            const int* p = (const int*)ws[j];
            int ok = 1;
            for (int i = 0; i < 16; i++) {
                int v = p[i];
                if (v < -127 || v > 127) ok = 0;
            }
            g_is32[j] = ok;
        }
    }
}

__global__ __launch_bounds__(256) void repack_all_kernel(
    const void* __restrict__ w0, const void* __restrict__ w1,
    const void* __restrict__ w2,
    int8_t* __restrict__ d0, int8_t* __restrict__ d1, int8_t* __restrict__ d2)
{
    const int which = blockIdx.y;
    const void* src = (which == 0) ? w0 : (which == 1) ? w1 : w2;
    int8_t*     dst = (which == 0) ? d0 : (which == 1) ? d1 : d2;

    const long long i = ((long long)blockIdx.x * blockDim.x + threadIdx.x) * 4;
    if (i >= WELEMS) return;
    if (g_is32[which]) {
        const int4 v = ((const int4*)src)[i >> 2];
        char4 c;
        c.x = (signed char)v.x; c.y = (signed char)v.y;
        c.z = (signed char)v.z; c.w = (signed char)v.w;
        *(char4*)(dst + i) = c;
    } else {
        *(char4*)(dst + i) = ((const char4*)src)[i >> 2];
    }
}

// ---------------------------------------------------------------------------
// Kernel 0: per-token dynamic int8 quantization of x
// ---------------------------------------------------------------------------
__global__ __launch_bounds__(256) void quant_x_kernel(const float* __restrict__ x) {
    const int row = blockIdx.x;
    const float4* xr = (const float4*)(x + (size_t)row * HDIM);
    const int nv = HDIM / 4;

    float m = 0.0f;
    for (int i = threadIdx.x; i < nv; i += blockDim.x) {
        float4 v = xr[i];
        m = fmaxf(m, fmaxf(fmaxf(fabsf(v.x), fabsf(v.y)), fmaxf(fabsf(v.z), fabsf(v.w))));
    }
    __shared__ float red[32];
    #pragma unroll
    for (int o = 16; o; o >>= 1) m = fmaxf(m, __shfl_xor_sync(0xFFFFFFFFu, m, o));
    if ((threadIdx.x & 31) == 0) red[threadIdx.x >> 5] = m;
    __syncthreads();
    if (threadIdx.x < 32) {
        float v = (threadIdx.x < (blockDim.x >> 5)) ? red[threadIdx.x] : 0.0f;
        #pragma unroll
        for (int o = 16; o; o >>= 1) v = fmaxf(v, __shfl_xor_sync(0xFFFFFFFFu, v, o));
        if (threadIdx.x == 0) red[0] = v;
    }
    __syncthreads();
    const float s = fmaxf(red[0] / 127.0f, 1e-8f);
    if (threadIdx.x == 0) g_sx[row] = s;

    char4* qr = (char4*)(g_qx + (size_t)row * HDIM);
    for (int i = threadIdx.x; i < nv; i += blockDim.x) {
        float4 v = xr[i];
        char4 q;
        q.x = (signed char)(int)fminf(fmaxf(rintf(v.x / s), -127.0f), 127.0f);
        q.y = (signed char)(int)fminf(fmaxf(rintf(v.y / s), -127.0f), 127.0f);
        q.z = (signed char)(int)fminf(fmaxf(rintf(v.z / s), -127.0f), 127.0f);
        q.w = (signed char)(int)fminf(fmaxf(rintf(v.w / s), -127.0f), 127.0f);
        qr[i] = q;
    }
}

// ---------------------------------------------------------------------------
// fc1 HYBRID v2: 1024 threads, BM=128, BN=128, BK=128, 3-stage ring, 1 CTA/SM.
//   warps 0-7  : IMMA GATE on cols [n0, n0+64)  (4m x 2n, 32x32 tile, 32 acc)
//   warps 8-15 : IMMA UP   on cols [n0, n0+64)  (identical fragments)
//     -> 4 IMMA warps/SMSP (R7-proven density), results merged via smem.
//   warps 16-31: dp4a on cols [n0+64, n0+128), 4r x 4c x 2 gemms = 32 acc.
// ---------------------------------------------------------------------------
__global__ __launch_bounds__(1024, 1) void fc1_kernel(
    const float* __restrict__ gsp, const float* __restrict__ usp,
    const float* __restrict__ disp)
{
    extern __shared__ __align__(128) int8_t smem[];
    const uint32_t sb = smem_u32(smem);

    const int tid = threadIdx.x;
    const int m0 = blockIdx.x * 128;   // M fastest -> weight L2 reuse
    const int n0 = blockIdx.y * 128;

    auto load_stage = [&](int s) {
        const uint32_t base = sb + (uint32_t)(s % 3) * FC1_STG;
        const int kb = s * 128;
        const int r = tid >> 3, c = (tid & 7) * 16;   // 1024 threads = 1024 chunks
        cp16(base + r * SSTR + c,         g_qx  + (size_t)(m0 + r) * HDIM + kb + c);
        cp16(base + 18432 + r * SSTR + c, g_w8g + (size_t)(n0 + r) * HDIM + kb + c);
        cp16(base + 36864 + r * SSTR + c, g_w8u + (size_t)(n0 + r) * HDIM + kb + c);
    };

    const int S = HDIM / 128;  // 28
    load_stage(0); cp_commit();
    load_stage(1); cp_commit();

    if (tid < 512) {
        // ===== IMMA: warps 0-7 gate, warps 8-15 up; single gemm per warp =====
        const int warp = tid >> 5, lane = tid & 31;
        const int wg = warp >> 3;            // 0 = gate, 1 = up
        const int w7 = warp & 7;
        const int wm = w7 >> 1, wn = w7 & 1;
        const int g  = lane >> 2, tg = lane & 3;
        const uint32_t aoff = (uint32_t)(((lane & 7) + ((lane >> 3) & 1) * 8) * SSTR + (lane >> 4) * 16);
        const uint32_t boff = (uint32_t)(((lane & 7) + (lane >> 4) * 8) * SSTR + ((lane >> 3) & 1) * 16);
        const uint32_t wsel = wg ? 36864u : 18432u;

        int acc[2][4][4] = {};

        for (int s = 0; s < S; s++) {
            cp_wait<1>();
            __syncthreads();
            if (s + 2 < S) load_stage(s + 2);
            cp_commit();

            const uint32_t base = sb + (uint32_t)(s % 3) * FC1_STG;
            const uint32_t abase = base + (uint32_t)(wm * 32) * SSTR + aoff;
            const uint32_t bbase = base + wsel + (uint32_t)(wn * 32) * SSTR + boff;

            #pragma unroll
            for (int ks = 0; ks < 4; ks++) {
                uint32_t a[2][4];
                ldsm_x4(a[0], abase + ks * 32);
                ldsm_x4(a[1], abase + 16 * SSTR + ks * 32);
                #pragma unroll
                for (int p = 0; p < 2; p++) {
                    uint32_t bb[4];
                    ldsm_x4(bb, bbase + p * 16 * SSTR + ks * 32);
                    #pragma unroll
                    for (int mt = 0; mt < 2; mt++) {
                        mma_s8(acc[mt][2 * p],     a[mt], bb[0], bb[1]);
                        mma_s8(acc[mt][2 * p + 1], a[mt], bb[2], bb[3]);
                    }
                }
            }
        }

        // ---- epilogue: up warps publish int32 to smem; gate warps combine ----
        cp_wait<0>();
        __syncthreads();
        int* ex = (int*)smem;   // 128 rows x 64 cols, stride 65 (33KB, dead stage buf)
        if (wg == 1) {
            #pragma unroll
            for (int mt = 0; mt < 2; mt++) {
                const int rr = wm * 32 + mt * 16 + g;
                #pragma unroll
                for (int nt = 0; nt < 4; nt++) {
                    const int cc = wn * 32 + nt * 8 + tg * 2;
                    ex[rr * 65 + cc]           = acc[mt][nt][0];
                    ex[rr * 65 + cc + 1]       = acc[mt][nt][1];
                    ex[(rr + 8) * 65 + cc]     = acc[mt][nt][2];
                    ex[(rr + 8) * 65 + cc + 1] = acc[mt][nt][3];
                }
            }
        }
        __syncthreads();
        if (wg == 0) {
            const float gscale = *gsp, uscale = *usp, dis = *disp;
            #pragma unroll
            for (int mt = 0; mt < 2; mt++) {
                const int rr = wm * 32 + mt * 16 + g;
                const int r0 = m0 + rr;
                const float s0 = g_sx[r0], s1 = g_sx[r0 + 8];
                #pragma unroll
                for (int nt = 0; nt < 4; nt++) {
                    const int cc = wn * 32 + nt * 8 + tg * 2;
                    const int c = n0 + cc;
                    char2 v0, v1;
                    v0.x = qsilu(acc[mt][nt][0], ex[rr * 65 + cc],           s0, gscale, uscale, dis);
                    v0.y = qsilu(acc[mt][nt][1], ex[rr * 65 + cc + 1],       s0, gscale, uscale, dis);
                    v1.x = qsilu(acc[mt][nt][2], ex[(rr + 8) * 65 + cc],     s1, gscale, uscale, dis);
                    v1.y = qsilu(acc[mt][nt][3], ex[(rr + 8) * 65 + cc + 1], s1, gscale, uscale, dis);
                    *(char2*)&g_qh[(size_t)r0 * IDIM + c]       = v0;
                    *(char2*)&g_qh[(size_t)(r0 + 8) * IDIM + c] = v1;
                }
            }
        }
    } else {
        // ===== dp4a: 16 warps, cols [n0+64, n0+128), 4r x 4c x 2 gemms =====
        const int wt = tid - 512;            // 0..511
        const int ty = wt >> 4, tx = wt & 15;  // ty 0..31 (4 rows each), tx 0..15

        int ag[4][4] = {};
        int au[4][4] = {};

        for (int s = 0; s < S; s++) {
            cp_wait<1>();
            __syncthreads();
            if (s + 2 < S) load_stage(s + 2);
            cp_commit();

            const int so = (s % 3) * FC1_STG;
            const int8_t* Ab = smem + so + ty * 4 * SSTR;
            const int8_t* Gb = smem + so + 18432 + (64 + tx) * SSTR;
            const int8_t* Ub = smem + so + 36864 + (64 + tx) * SSTR;

            #pragma unroll
            for (int k4 = 0; k4 < 8; k4++) {
                int4 a4[4];
                #pragma unroll
                for (int i = 0; i < 4; i++)
                    a4[i] = *(const int4*)(Ab + i * SSTR + k4 * 16);
                #pragma unroll
                for (int j = 0; j < 4; j++) {
                    const int4 bg4 = *(const int4*)(Gb + j * 16 * SSTR + k4 * 16);
                    const int4 bu4 = *(const int4*)(Ub + j * 16 * SSTR + k4 * 16);
                    #pragma unroll
                    for (int i = 0; i < 4; i++) {
                        dp4x4(ag[i][j], a4[i], bg4);
                        dp4x4(au[i][j], a4[i], bu4);
                    }
                }
            }
        }

        cp_wait<0>();
        __syncthreads();   // match IMMA epilogue barrier 1
        __syncthreads();   // match IMMA epilogue barrier 2

        const float gscale = *gsp, uscale = *usp, dis = *disp;
        #pragma unroll
        for (int i = 0; i < 4; i++) {
            const int row = m0 + ty * 4 + i;
            const float srow = g_sx[row];
            #pragma unroll
            for (int j = 0; j < 4; j++) {
                const int col = n0 + 64 + tx + 16 * j;
                g_qh[(size_t)row * IDIM + col] =
                    qsilu(ag[i][j], au[i][j], srow, gscale, uscale, dis);
            }
        }
    }
}

// ---------------------------------------------------------------------------
// fc2 HYBRID (R9 exact): 512 threads, BM=128, BN=128, BK=128, 3-stage ring.
// ---------------------------------------------------------------------------
__global__ __launch_bounds__(512, 1) void fc2_kernel(
    const float* __restrict__ dsp, const float* __restrict__ disp,
    float* __restrict__ out)
{
    extern __shared__ __align__(128) int8_t smem[];
    const uint32_t sb = smem_u32(smem);

    const int tid = threadIdx.x;
    const int m0 = blockIdx.x * 128;
    const int n0 = blockIdx.y * 128;

    auto load_stage = [&](int s) {
        const uint32_t base = sb + (uint32_t)(s % 3) * FC2_STG;
        const int kb = s * 128;
        #pragma unroll
        for (int i = 0; i < 2; i++) {
            const int idx = tid + i * 512;
            const int r = idx >> 3, c = (idx & 7) * 16;
            cp16(base + r * SSTR + c,         g_qh  + (size_t)(m0 + r) * IDIM + kb + c);
            cp16(base + 18432 + r * SSTR + c, g_w8d + (size_t)(n0 + r) * IDIM + kb + c);
        }
    };

    const int S = IDIM / 128;  // 148
    load_stage(0); cp_commit();
    load_stage(1); cp_commit();

    if (tid < 256) {
        // ===================== IMMA half =====================
        const int warp = tid >> 5, lane = tid & 31;
        const int wm = warp >> 1, wn = warp & 1;
        const int g  = lane >> 2, tg = lane & 3;
        const uint32_t aoff = (uint32_t)(((lane & 7) + ((lane >> 3) & 1) * 8) * SSTR + (lane >> 4) * 16);
        const uint32_t boff = (uint32_t)(((lane & 7) + (lane >> 4) * 8) * SSTR + ((lane >> 3) & 1) * 16);

        int acc[2][4][4] = {};

        for (int s = 0; s < S; s++) {
            cp_wait<1>();
            __syncthreads();
            if (s + 2 < S) load_stage(s + 2);
            cp_commit();

            const uint32_t base = sb + (uint32_t)(s % 3) * FC2_STG;
            const uint32_t abase = base + (uint32_t)(wm * 32) * SSTR + aoff;
            const uint32_t bbase = base + 18432 + (uint32_t)(wn * 32) * SSTR + boff;

            #pragma unroll
            for (int ks = 0; ks < 4; ks++) {
                uint32_t a[2][4];
                ldsm_x4(a[0], abase + ks * 32);
                ldsm_x4(a[1], abase + 16 * SSTR + ks * 32);
                #pragma unroll
                for (int p = 0; p < 2; p++) {
                    uint32_t bb[4];
                    ldsm_x4(bb, bbase + p * 16 * SSTR + ks * 32);
                    #pragma unroll
                    for (int mt = 0; mt < 2; mt++) {
                        mma_s8(acc[mt][2 * p],     a[mt], bb[0], bb[1]);
                        mma_s8(acc[mt][2 * p + 1], a[mt], bb[2], bb[3]);
                    }
                }
            }
        }

        const float oscale = (*disp) * (*dsp);
        #pragma unroll
        for (int mt = 0; mt < 2; mt++) {
            const int r0 = m0 + wm * 32 + mt * 16 + g;
            #pragma unroll
            for (int nt = 0; nt < 4; nt++) {
                const int c = n0 + wn * 32 + nt * 8 + tg * 2;
                float2 v0, v1;
                v0.x = (float)acc[mt][nt][0] * oscale;
                v0.y = (float)acc[mt][nt][1] * oscale;
                v1.x = (float)acc[mt][nt][2] * oscale;
                v1.y = (float)acc[mt][nt][3] * oscale;
                *(float2*)&out[(size_t)r0 * HDIM + c]       = v0;
                *(float2*)&out[(size_t)(r0 + 8) * HDIM + c] = v1;
            }
        }
    } else {
        // ===================== dp4a half =====================
        const int wt = tid - 256;
        const int ty = wt >> 4, tx = wt & 15;

        int acc[8][4] = {};

        for (int s = 0; s < S; s++) {
            cp_wait<1>();
            __syncthreads();
            if (s + 2 < S) load_stage(s + 2);
            cp_commit();

            const int so = (s % 3) * FC2_STG;
            const int8_t* Ab = smem + so + ty * 8 * SSTR;
            const int8_t* Bb = smem + so + 18432 + (64 + tx) * SSTR;

            #pragma unroll
            for (int k4 = 0; k4 < 8; k4++) {
                int4 a4[8];
                #pragma unroll
                for (int i = 0; i < 8; i++)
                    a4[i] = *(const int4*)(Ab + i * SSTR + k4 * 16);
                #pragma unroll
                for (int j = 0; j < 4; j++) {
                    const int4 b4 = *(const int4*)(Bb + j * 16 * SSTR + k4 * 16);
                    #pragma unroll
                    for (int i = 0; i < 8; i++)
                        dp4x4(acc[i][j], a4[i], b4);
                }
            }
        }

        const float oscale = (*disp) * (*dsp);
        #pragma unroll
        for (int i = 0; i < 8; i++) {
            const int row = m0 + ty * 8 + i;
            #pragma unroll
            for (int j = 0; j < 4; j++) {
                const int col = n0 + 64 + tx + 16 * j;
                out[(size_t)row * HDIM + col] = (float)acc[i][j] * oscale;
            }
        }
    }
}

// ---------------------------------------------------------------------------
// Entry point
// ---------------------------------------------------------------------------
extern "C" void kernel_launch(void* const* d_in, const int* in_sizes, int n_in,
                              void* d_out, int out_size) {
    const int XSZ = T_TOKENS * HDIM;

    int xi = -1, widx[3] = {-1,-1,-1}, sidx[4] = {-1,-1,-1,-1};
    int nw = 0, ns = 0;
    for (int i = 0; i < n_in; i++) {
        if (in_sizes[i] == XSZ) xi = i;
        else if ((long long)in_sizes[i] == WELEMS) { if (nw < 3) widx[nw++] = i; }
        else if (in_sizes[i] == 1) { if (ns < 4) sidx[ns++] = i; }
    }

    const float *x, *gs, *us, *ds, *dis;
    const void *gw, *uw, *dw;

    if (xi == 0) {
        x   = (const float*)d_in[xi];
        gw  = d_in[widx[0]];
        uw  = d_in[widx[1]];
        dw  = d_in[widx[2]];
        gs  = (const float*)d_in[sidx[0]];
        us  = (const float*)d_in[sidx[1]];
        ds  = (const float*)d_in[sidx[2]];
        dis = (const float*)d_in[sidx[3]];
    } else {
        x   = (const float*)d_in[xi];
        dw  = d_in[widx[0]];
        gw  = d_in[widx[1]];
        uw  = d_in[widx[2]];
        dis = (const float*)d_in[sidx[0]];
        ds  = (const float*)d_in[sidx[1]];
        gs  = (const float*)d_in[sidx[2]];
        us  = (const float*)d_in[sidx[3]];
    }

    float* out = (float*)d_out;

    static int smem_set = 0;
    if (!smem_set) {
        cudaFuncSetAttribute(fc1_kernel, cudaFuncAttributeMaxDynamicSharedMemorySize, FC1_SMEM);
        cudaFuncSetAttribute(fc2_kernel, cudaFuncAttributeMaxDynamicSharedMemorySize, FC2_SMEM);
        smem_set = 1;
    }

    detect_kernel<<<1, 32>>>(gw, uw, dw);

    int8_t* w8g; cudaGetSymbolAddress((void**)&w8g, g_w8g);
    int8_t* w8u; cudaGetSymbolAddress((void**)&w8u, g_w8u);
    int8_t* w8d; cudaGetSymbolAddress((void**)&w8d, g_w8d);
    const int rp_blocks = (int)((WELEMS / 4 + 255) / 256);
    repack_all_kernel<<<dim3(rp_blocks, 3), 256>>>(gw, uw, dw, w8g, w8u, w8d);

    quant_x_kernel<<<T_TOKENS, 256>>>(x);

    // M fastest (grid.x) so concurrent CTAs share weight stripes in L2.
    fc1_kernel<<<dim3(T_TOKENS / 128, IDIM / 128), 1024, FC1_SMEM>>>(gs, us, dis);
    fc2_kernel<<<dim3(T_TOKENS / 128, HDIM / 128), 512, FC2_SMEM>>>(ds, dis, out);
}

// round 16
// speedup vs baseline: 1.3890x; 1.0293x over previous
#include <cuda_runtime.h>
#include <cstdint>
#include <math.h>

// Problem dims
#define T_TOKENS 2048
#define HDIM     3584
#define IDIM     18944
#define WELEMS   ((long long)IDIM * HDIM)

// ---------------------------------------------------------------------------
// Scratch (device globals)
// ---------------------------------------------------------------------------
__device__ __align__(16) int8_t g_qx[(size_t)T_TOKENS * HDIM];
__device__ float               g_sx[T_TOKENS];
__device__ __align__(16) int8_t g_qh[(size_t)T_TOKENS * IDIM];
__device__ __align__(16) int8_t g_w8g[WELEMS];
__device__ __align__(16) int8_t g_w8u[WELEMS];
__device__ __align__(16) int8_t g_w8d[WELEMS];
__device__ int g_is32[3];

// ---------------------------------------------------------------------------
// Helpers
// ---------------------------------------------------------------------------
__device__ __forceinline__ uint32_t smem_u32(const void* p) {
    return (uint32_t)__cvta_generic_to_shared(p);
}
__device__ __forceinline__ void cp16(uint32_t dst, const void* src) {
    asm volatile("cp.async.cg.shared.global [%0], [%1], 16;" :: "r"(dst), "l"(src));
}
__device__ __forceinline__ void cp_commit() {
    asm volatile("cp.async.commit_group;");
}
template <int N>
__device__ __forceinline__ void cp_wait() {
    asm volatile("cp.async.wait_group %0;" :: "n"(N));
}
__device__ __forceinline__ void ldsm_x4(uint32_t* r, uint32_t saddr) {
    asm volatile("ldmatrix.sync.aligned.m8n8.x4.shared.b16 {%0,%1,%2,%3}, [%4];"
                 : "=r"(r[0]), "=r"(r[1]), "=r"(r[2]), "=r"(r[3]) : "r"(saddr));
}
__device__ __forceinline__ void mma_s8(int* c, const uint32_t* a, uint32_t b0, uint32_t b1) {
    asm volatile(
        "mma.sync.aligned.m16n8k32.row.col.s32.s8.s8.s32 "
        "{%0,%1,%2,%3},{%4,%5,%6,%7},{%8,%9},{%0,%1,%2,%3};"
        : "+r"(c[0]), "+r"(c[1]), "+r"(c[2]), "+r"(c[3])
        : "r"(a[0]), "r"(a[1]), "r"(a[2]), "r"(a[3]), "r"(b0), "r"(b1));
}
__device__ __forceinline__ signed char qsilu(int gi, int ui, float srow,
                                             float gs, float us, float dis) {
    float gv = (float)gi * srow * gs;
    float uv = (float)ui * srow * us;
    float h  = (gv / (1.0f + expf(-gv))) * uv;
    float q  = rintf(h / dis);
    q = fminf(fmaxf(q, -127.0f), 127.0f);
    return (signed char)(int)q;
}
__device__ __forceinline__ void dp4x4(int& acc, const int4& a, const int4& b) {
    acc = __dp4a(a.x, b.x, acc);
    acc = __dp4a(a.y, b.y, acc);
    acc = __dp4a(a.z, b.z, acc);
    acc = __dp4a(a.w, b.w, acc);
}

constexpr int SSTR = 144;     // 128B row + 16B pad (16B-aligned, conflict-free)
// fc1: 3 stages x (A 18432 | G 18432 | U 18432)
#define FC1_STG   55296
#define FC1_SMEM  (3 * FC1_STG)    // 165888, 1 CTA/SM (also holds 66KB epilogue exchange)
// fc2 (R9 exact): 3 stages x (A 18432 | B 18432)
#define FC2_STG   36864
#define FC2_SMEM  (3 * FC2_STG)    // 110592

// ---------------------------------------------------------------------------
// Dtype detector + fused repack (R9-proven)
// ---------------------------------------------------------------------------
__global__ void detect_kernel(const void* w0, const void* w1, const void* w2) {
    if (threadIdx.x == 0 && blockIdx.x == 0) {
        const void* ws[3] = {w0, w1, w2};
        for (int j = 0; j < 3; j++) {
            const int* p = (const int*)ws[j];
            int ok = 1;
            for (int i = 0; i < 16; i++) {
                int v = p[i];
                if (v < -127 || v > 127) ok = 0;
            }
            g_is32[j] = ok;
        }
    }
}

__global__ __launch_bounds__(256) void repack_all_kernel(
    const void* __restrict__ w0, const void* __restrict__ w1,
    const void* __restrict__ w2,
    int8_t* __restrict__ d0, int8_t* __restrict__ d1, int8_t* __restrict__ d2)
{
    const int which = blockIdx.y;
    const void* src = (which == 0) ? w0 : (which == 1) ? w1 : w2;
    int8_t*     dst = (which == 0) ? d0 : (which == 1) ? d1 : d2;

    const long long i = ((long long)blockIdx.x * blockDim.x + threadIdx.x) * 4;
    if (i >= WELEMS) return;
    if (g_is32[which]) {
        const int4 v = ((const int4*)src)[i >> 2];
        char4 c;
        c.x = (signed char)v.x; c.y = (signed char)v.y;
        c.z = (signed char)v.z; c.w = (signed char)v.w;
        *(char4*)(dst + i) = c;
    } else {
        *(char4*)(dst + i) = ((const char4*)src)[i >> 2];
    }
}

// ---------------------------------------------------------------------------
// Kernel 0: per-token dynamic int8 quantization of x
// ---------------------------------------------------------------------------
__global__ __launch_bounds__(256) void quant_x_kernel(const float* __restrict__ x) {
    const int row = blockIdx.x;
    const float4* xr = (const float4*)(x + (size_t)row * HDIM);
    const int nv = HDIM / 4;

    float m = 0.0f;
    for (int i = threadIdx.x; i < nv; i += blockDim.x) {
        float4 v = xr[i];
        m = fmaxf(m, fmaxf(fmaxf(fabsf(v.x), fabsf(v.y)), fmaxf(fabsf(v.z), fabsf(v.w))));
    }
    __shared__ float red[32];
    #pragma unroll
    for (int o = 16; o; o >>= 1) m = fmaxf(m, __shfl_xor_sync(0xFFFFFFFFu, m, o));
    if ((threadIdx.x & 31) == 0) red[threadIdx.x >> 5] = m;
    __syncthreads();
    if (threadIdx.x < 32) {
        float v = (threadIdx.x < (blockDim.x >> 5)) ? red[threadIdx.x] : 0.0f;
        #pragma unroll
        for (int o = 16; o; o >>= 1) v = fmaxf(v, __shfl_xor_sync(0xFFFFFFFFu, v, o));
        if (threadIdx.x == 0) red[0] = v;
    }
    __syncthreads();
    const float s = fmaxf(red[0] / 127.0f, 1e-8f);
    if (threadIdx.x == 0) g_sx[row] = s;

    char4* qr = (char4*)(g_qx + (size_t)row * HDIM);
    for (int i = threadIdx.x; i < nv; i += blockDim.x) {
        float4 v = xr[i];
        char4 q;
        q.x = (signed char)(int)fminf(fmaxf(rintf(v.x / s), -127.0f), 127.0f);
        q.y = (signed char)(int)fminf(fmaxf(rintf(v.y / s), -127.0f), 127.0f);
        q.z = (signed char)(int)fminf(fmaxf(rintf(v.z / s), -127.0f), 127.0f);
        q.w = (signed char)(int)fminf(fmaxf(rintf(v.w / s), -127.0f), 127.0f);
        qr[i] = q;
    }
}

// ---------------------------------------------------------------------------
// fc1 GEMM-SPLIT: 512 threads, BM=128, BN=128, BK=128, 3-stage ring, 1 CTA/SM.
//   warps 0-7 : IMMA computes GATE over ALL 128 cols (4m x 2n, 32x64 warp
//               tile = exact R9-fc2 shape, 64 acc/thread -> no reg pressure)
//   warps 8-15: dp4a computes UP over ALL 128 cols (8r x 8c, 64 acc/thread)
// Epilogue: up int32 published to smem exchange; gate warps fuse SwiGLU.
// ---------------------------------------------------------------------------
__global__ __launch_bounds__(512, 1) void fc1_kernel(
    const float* __restrict__ gsp, const float* __restrict__ usp,
    const float* __restrict__ disp)
{
    extern __shared__ __align__(128) int8_t smem[];
    const uint32_t sb = smem_u32(smem);

    const int tid = threadIdx.x;
    const int m0 = blockIdx.x * 128;   // M fastest -> weight L2 reuse
    const int n0 = blockIdx.y * 128;

    auto load_stage = [&](int s) {
        const uint32_t base = sb + (uint32_t)(s % 3) * FC1_STG;
        const int kb = s * 128;
        #pragma unroll
        for (int i = 0; i < 2; i++) {
            const int idx = tid + i * 512;
            const int r = idx >> 3, c = (idx & 7) * 16;
            cp16(base + r * SSTR + c,         g_qx  + (size_t)(m0 + r) * HDIM + kb + c);
            cp16(base + 18432 + r * SSTR + c, g_w8g + (size_t)(n0 + r) * HDIM + kb + c);
            cp16(base + 36864 + r * SSTR + c, g_w8u + (size_t)(n0 + r) * HDIM + kb + c);
        }
    };

    const int S = HDIM / 128;  // 28
    load_stage(0); cp_commit();
    load_stage(1); cp_commit();

    int* ex = (int*)smem;   // epilogue exchange: 128 x 128 int32, stride 129 (66KB)

    if (tid < 256) {
        // ===== IMMA GATE: 8 warps, 4m x 2n, warp tile 32 x 64 (R9-fc2 shape) =====
        const int warp = tid >> 5, lane = tid & 31;
        const int wm = warp >> 1, wn = warp & 1;
        const int g  = lane >> 2, tg = lane & 3;
        const uint32_t aoff = (uint32_t)(((lane & 7) + ((lane >> 3) & 1) * 8) * SSTR + (lane >> 4) * 16);
        const uint32_t boff = (uint32_t)(((lane & 7) + (lane >> 4) * 8) * SSTR + ((lane >> 3) & 1) * 16);

        int acc[2][8][4] = {};

        for (int s = 0; s < S; s++) {
            cp_wait<1>();
            __syncthreads();
            if (s + 2 < S) load_stage(s + 2);
            cp_commit();

            const uint32_t base = sb + (uint32_t)(s % 3) * FC1_STG;
            const uint32_t abase = base + (uint32_t)(wm * 32) * SSTR + aoff;
            const uint32_t bbase = base + 18432 + (uint32_t)(wn * 64) * SSTR + boff;

            #pragma unroll
            for (int ks = 0; ks < 4; ks++) {
                uint32_t a[2][4];
                ldsm_x4(a[0], abase + ks * 32);
                ldsm_x4(a[1], abase + 16 * SSTR + ks * 32);
                #pragma unroll
                for (int p = 0; p < 4; p++) {
                    uint32_t bb[4];
                    ldsm_x4(bb, bbase + p * 16 * SSTR + ks * 32);
                    #pragma unroll
                    for (int mt = 0; mt < 2; mt++) {
                        mma_s8(acc[mt][2 * p],     a[mt], bb[0], bb[1]);
                        mma_s8(acc[mt][2 * p + 1], a[mt], bb[2], bb[3]);
                    }
                }
            }
        }

        // ---- epilogue: wait for up-warps' exchange, then fuse SwiGLU ----
        cp_wait<0>();
        __syncthreads();   // barrier E1: stage buffers dead; up warps write ex
        __syncthreads();   // barrier E2: ex visible

        const float gscale = *gsp, uscale = *usp, dis = *disp;
        #pragma unroll
        for (int mt = 0; mt < 2; mt++) {
            const int rr = wm * 32 + mt * 16 + g;
            const int r0 = m0 + rr;
            const float s0 = g_sx[r0], s1 = g_sx[r0 + 8];
            #pragma unroll
            for (int nt = 0; nt < 8; nt++) {
                const int cc = wn * 64 + nt * 8 + tg * 2;
                const int c = n0 + cc;
                char2 v0, v1;
                v0.x = qsilu(acc[mt][nt][0], ex[rr * 129 + cc],           s0, gscale, uscale, dis);
                v0.y = qsilu(acc[mt][nt][1], ex[rr * 129 + cc + 1],       s0, gscale, uscale, dis);
                v1.x = qsilu(acc[mt][nt][2], ex[(rr + 8) * 129 + cc],     s1, gscale, uscale, dis);
                v1.y = qsilu(acc[mt][nt][3], ex[(rr + 8) * 129 + cc + 1], s1, gscale, uscale, dis);
                *(char2*)&g_qh[(size_t)r0 * IDIM + c]       = v0;
                *(char2*)&g_qh[(size_t)(r0 + 8) * IDIM + c] = v1;
            }
        }
    } else {
        // ===== dp4a UP: 8 warps, all 128 cols, thread tile 8r x 8c =====
        const int wt = tid - 256;
        const int ty = wt >> 4, tx = wt & 15;   // rows ty*8..+8, cols tx+16j (j<8)

        int acc[8][8] = {};

        for (int s = 0; s < S; s++) {
            cp_wait<1>();
            __syncthreads();
            if (s + 2 < S) load_stage(s + 2);
            cp_commit();

            const int so = (s % 3) * FC1_STG;
            const int8_t* Ab = smem + so + ty * 8 * SSTR;
            const int8_t* Ub = smem + so + 36864 + tx * SSTR;

            #pragma unroll
            for (int k4 = 0; k4 < 8; k4++) {
                int4 a4[8];
                #pragma unroll
                for (int i = 0; i < 8; i++)
                    a4[i] = *(const int4*)(Ab + i * SSTR + k4 * 16);
                #pragma unroll
                for (int j = 0; j < 8; j++) {
                    const int4 b4 = *(const int4*)(Ub + j * 16 * SSTR + k4 * 16);
                    #pragma unroll
                    for (int i = 0; i < 8; i++)
                        dp4x4(acc[i][j], a4[i], b4);
                }
            }
        }

        // ---- epilogue: publish up int32 to exchange ----
        cp_wait<0>();
        __syncthreads();   // barrier E1
        #pragma unroll
        for (int i = 0; i < 8; i++) {
            const int rr = ty * 8 + i;
            #pragma unroll
            for (int j = 0; j < 8; j++)
                ex[rr * 129 + tx + 16 * j] = acc[i][j];
        }
        __syncthreads();   // barrier E2
    }
}

// ---------------------------------------------------------------------------
// fc2 HYBRID (R9 exact): 512 threads, BM=128, BN=128, BK=128, 3-stage ring.
// ---------------------------------------------------------------------------
__global__ __launch_bounds__(512, 1) void fc2_kernel(
    const float* __restrict__ dsp, const float* __restrict__ disp,
    float* __restrict__ out)
{
    extern __shared__ __align__(128) int8_t smem[];
    const uint32_t sb = smem_u32(smem);

    const int tid = threadIdx.x;
    const int m0 = blockIdx.x * 128;
    const int n0 = blockIdx.y * 128;

    auto load_stage = [&](int s) {
        const uint32_t base = sb + (uint32_t)(s % 3) * FC2_STG;
        const int kb = s * 128;
        #pragma unroll
        for (int i = 0; i < 2; i++) {
            const int idx = tid + i * 512;
            const int r = idx >> 3, c = (idx & 7) * 16;
            cp16(base + r * SSTR + c,         g_qh  + (size_t)(m0 + r) * IDIM + kb + c);
            cp16(base + 18432 + r * SSTR + c, g_w8d + (size_t)(n0 + r) * IDIM + kb + c);
        }
    };

    const int S = IDIM / 128;  // 148
    load_stage(0); cp_commit();
    load_stage(1); cp_commit();

    if (tid < 256) {
        // ===================== IMMA half =====================
        const int warp = tid >> 5, lane = tid & 31;
        const int wm = warp >> 1, wn = warp & 1;
        const int g  = lane >> 2, tg = lane & 3;
        const uint32_t aoff = (uint32_t)(((lane & 7) + ((lane >> 3) & 1) * 8) * SSTR + (lane >> 4) * 16);
        const uint32_t boff = (uint32_t)(((lane & 7) + (lane >> 4) * 8) * SSTR + ((lane >> 3) & 1) * 16);

        int acc[2][4][4] = {};

        for (int s = 0; s < S; s++) {
            cp_wait<1>();
            __syncthreads();
            if (s + 2 < S) load_stage(s + 2);
            cp_commit();

            const uint32_t base = sb + (uint32_t)(s % 3) * FC2_STG;
            const uint32_t abase = base + (uint32_t)(wm * 32) * SSTR + aoff;
            const uint32_t bbase = base + 18432 + (uint32_t)(wn * 32) * SSTR + boff;

            #pragma unroll
            for (int ks = 0; ks < 4; ks++) {
                uint32_t a[2][4];
                ldsm_x4(a[0], abase + ks * 32);
                ldsm_x4(a[1], abase + 16 * SSTR + ks * 32);
                #pragma unroll
                for (int p = 0; p < 2; p++) {
                    uint32_t bb[4];
                    ldsm_x4(bb, bbase + p * 16 * SSTR + ks * 32);
                    #pragma unroll
                    for (int mt = 0; mt < 2; mt++) {
                        mma_s8(acc[mt][2 * p],     a[mt], bb[0], bb[1]);
                        mma_s8(acc[mt][2 * p + 1], a[mt], bb[2], bb[3]);
                    }
                }
            }
        }

        const float oscale = (*disp) * (*dsp);
        #pragma unroll
        for (int mt = 0; mt < 2; mt++) {
            const int r0 = m0 + wm * 32 + mt * 16 + g;
            #pragma unroll
            for (int nt = 0; nt < 4; nt++) {
                const int c = n0 + wn * 32 + nt * 8 + tg * 2;
                float2 v0, v1;
                v0.x = (float)acc[mt][nt][0] * oscale;
                v0.y = (float)acc[mt][nt][1] * oscale;
                v1.x = (float)acc[mt][nt][2] * oscale;
                v1.y = (float)acc[mt][nt][3] * oscale;
                *(float2*)&out[(size_t)r0 * HDIM + c]       = v0;
                *(float2*)&out[(size_t)(r0 + 8) * HDIM + c] = v1;
            }
        }
    } else {
        // ===================== dp4a half =====================
        const int wt = tid - 256;
        const int ty = wt >> 4, tx = wt & 15;

        int acc[8][4] = {};

        for (int s = 0; s < S; s++) {
            cp_wait<1>();
            __syncthreads();
            if (s + 2 < S) load_stage(s + 2);
            cp_commit();

            const int so = (s % 3) * FC2_STG;
            const int8_t* Ab = smem + so + ty * 8 * SSTR;
            const int8_t* Bb = smem + so + 18432 + (64 + tx) * SSTR;

            #pragma unroll
            for (int k4 = 0; k4 < 8; k4++) {
                int4 a4[8];
                #pragma unroll
                for (int i = 0; i < 8; i++)
                    a4[i] = *(const int4*)(Ab + i * SSTR + k4 * 16);
                #pragma unroll
                for (int j = 0; j < 4; j++) {
                    const int4 b4 = *(const int4*)(Bb + j * 16 * SSTR + k4 * 16);
                    #pragma unroll
                    for (int i = 0; i < 8; i++)
                        dp4x4(acc[i][j], a4[i], b4);
                }
            }
        }

        const float oscale = (*disp) * (*dsp);
        #pragma unroll
        for (int i = 0; i < 8; i++) {
            const int row = m0 + ty * 8 + i;
            #pragma unroll
            for (int j = 0; j < 4; j++) {
                const int col = n0 + 64 + tx + 16 * j;
                out[(size_t)row * HDIM + col] = (float)acc[i][j] * oscale;
            }
        }
    }
}

// ---------------------------------------------------------------------------
// Entry point
// ---------------------------------------------------------------------------
extern "C" void kernel_launch(void* const* d_in, const int* in_sizes, int n_in,
                              void* d_out, int out_size) {
    const int XSZ = T_TOKENS * HDIM;

    int xi = -1, widx[3] = {-1,-1,-1}, sidx[4] = {-1,-1,-1,-1};
    int nw = 0, ns = 0;
    for (int i = 0; i < n_in; i++) {
        if (in_sizes[i] == XSZ) xi = i;
        else if ((long long)in_sizes[i] == WELEMS) { if (nw < 3) widx[nw++] = i; }
        else if (in_sizes[i] == 1) { if (ns < 4) sidx[ns++] = i; }
    }

    const float *x, *gs, *us, *ds, *dis;
    const void *gw, *uw, *dw;

    if (xi == 0) {
        x   = (const float*)d_in[xi];
        gw  = d_in[widx[0]];
        uw  = d_in[widx[1]];
        dw  = d_in[widx[2]];
        gs  = (const float*)d_in[sidx[0]];
        us  = (const float*)d_in[sidx[1]];
        ds  = (const float*)d_in[sidx[2]];
        dis = (const float*)d_in[sidx[3]];
    } else {
        x   = (const float*)d_in[xi];
        dw  = d_in[widx[0]];
        gw  = d_in[widx[1]];
        uw  = d_in[widx[2]];
        dis = (const float*)d_in[sidx[0]];
        ds  = (const float*)d_in[sidx[1]];
        gs  = (const float*)d_in[sidx[2]];
        us  = (const float*)d_in[sidx[3]];
    }

    float* out = (float*)d_out;

    static int smem_set = 0;
    if (!smem_set) {
        cudaFuncSetAttribute(fc1_kernel, cudaFuncAttributeMaxDynamicSharedMemorySize, FC1_SMEM);
        cudaFuncSetAttribute(fc2_kernel, cudaFuncAttributeMaxDynamicSharedMemorySize, FC2_SMEM);
        smem_set = 1;
    }

    detect_kernel<<<1, 32>>>(gw, uw, dw);

    int8_t* w8g; cudaGetSymbolAddress((void**)&w8g, g_w8g);
    int8_t* w8u; cudaGetSymbolAddress((void**)&w8u, g_w8u);
    int8_t* w8d; cudaGetSymbolAddress((void**)&w8d, g_w8d);
    const int rp_blocks = (int)((WELEMS / 4 + 255) / 256);
    repack_all_kernel<<<dim3(rp_blocks, 3), 256>>>(gw, uw, dw, w8g, w8u, w8d);

    quant_x_kernel<<<T_TOKENS, 256>>>(x);

    // M fastest (grid.x) so concurrent CTAs share weight stripes in L2.
    fc1_kernel<<<dim3(T_TOKENS / 128, IDIM / 128), 512, FC1_SMEM>>>(gs, us, dis);
    fc2_kernel<<<dim3(T_TOKENS / 128, HDIM / 128), 512, FC2_SMEM>>>(ds, dis, out);
}

// round 17
// speedup vs baseline: 1.4241x; 1.0253x over previous
#include <cuda_runtime.h>
#include <cstdint>
#include <math.h>

// Problem dims
#define T_TOKENS 2048
#define HDIM     3584
#define IDIM     18944
#define WELEMS   ((long long)IDIM * HDIM)

// ---------------------------------------------------------------------------
// Scratch (device globals)
// ---------------------------------------------------------------------------
__device__ __align__(16) int8_t g_qx[(size_t)T_TOKENS * HDIM];
__device__ float               g_sx[T_TOKENS];
__device__ __align__(16) int8_t g_qh[(size_t)T_TOKENS * IDIM];
__device__ __align__(16) int8_t g_w8g[WELEMS];
__device__ __align__(16) int8_t g_w8u[WELEMS];
__device__ __align__(16) int8_t g_w8d[WELEMS];
__device__ int g_is32[3];

// ---------------------------------------------------------------------------
// Helpers
// ---------------------------------------------------------------------------
__device__ __forceinline__ uint32_t smem_u32(const void* p) {
    return (uint32_t)__cvta_generic_to_shared(p);
}
__device__ __forceinline__ void cp16(uint32_t dst, const void* src) {
    asm volatile("cp.async.cg.shared.global [%0], [%1], 16;" :: "r"(dst), "l"(src));
}
__device__ __forceinline__ void cp_commit() {
    asm volatile("cp.async.commit_group;");
}
template <int N>
__device__ __forceinline__ void cp_wait() {
    asm volatile("cp.async.wait_group %0;" :: "n"(N));
}
__device__ __forceinline__ void ldsm_x4(uint32_t* r, uint32_t saddr) {
    asm volatile("ldmatrix.sync.aligned.m8n8.x4.shared.b16 {%0,%1,%2,%3}, [%4];"
                 : "=r"(r[0]), "=r"(r[1]), "=r"(r[2]), "=r"(r[3]) : "r"(saddr));
}
__device__ __forceinline__ void mma_s8(int* c, const uint32_t* a, uint32_t b0, uint32_t b1) {
    asm volatile(
        "mma.sync.aligned.m16n8k32.row.col.s32.s8.s8.s32 "
        "{%0,%1,%2,%3},{%4,%5,%6,%7},{%8,%9},{%0,%1,%2,%3};"
        : "+r"(c[0]), "+r"(c[1]), "+r"(c[2]), "+r"(c[3])
        : "r"(a[0]), "r"(a[1]), "r"(a[2]), "r"(a[3]), "r"(b0), "r"(b1));
}
__device__ __forceinline__ signed char qsilu(int gi, int ui, float srow,
                                             float gs, float us, float dis) {
    float gv = (float)gi * srow * gs;
    float uv = (float)ui * srow * us;
    float h  = (gv / (1.0f + expf(-gv))) * uv;
    float q  = rintf(h / dis);
    q = fminf(fmaxf(q, -127.0f), 127.0f);
    return (signed char)(int)q;
}
__device__ __forceinline__ void dp4x4(int& acc, const int4& a, const int4& b) {
    acc = __dp4a(a.x, b.x, acc);
    acc = __dp4a(a.y, b.y, acc);
    acc = __dp4a(a.z, b.z, acc);
    acc = __dp4a(a.w, b.w, acc);
}

constexpr int SSTR = 144;     // 128B row + 16B pad (16B-aligned, conflict-free)
// fc1 (R9 exact): 3 stages x (A 18432 | G 18432 | U 18432)
#define FC1_STG   55296
#define FC1_SMEM  (3 * FC1_STG)    // 165888
// fc2 (R9 exact): 3 stages x (A 18432 | B 18432)
#define FC2_STG   36864
#define FC2_SMEM  (3 * FC2_STG)    // 110592

// ---------------------------------------------------------------------------
// Dtype detector
// ---------------------------------------------------------------------------
__global__ void detect_kernel(const void* w0, const void* w1, const void* w2) {
    if (threadIdx.x == 0 && blockIdx.x == 0) {
        const void* ws[3] = {w0, w1, w2};
        for (int j = 0; j < 3; j++) {
            const int* p = (const int*)ws[j];
            int ok = 1;
            for (int i = 0; i < 16; i++) {
                int v = p[i];
                if (v < -127 || v > 127) ok = 0;
            }
            g_is32[j] = ok;
        }
    }
}

// ---------------------------------------------------------------------------
// Repack v2: 16 elements/thread. int32 path: 4x int4 loads -> 1x int4 store.
// int8 path: 1x int4 load -> 1x int4 store. Full 128B store sectors per warp.
// ---------------------------------------------------------------------------
__global__ __launch_bounds__(256) void repack_all_kernel(
    const void* __restrict__ w0, const void* __restrict__ w1,
    const void* __restrict__ w2,
    int8_t* __restrict__ d0, int8_t* __restrict__ d1, int8_t* __restrict__ d2)
{
    const int which = blockIdx.y;
    const void* src = (which == 0) ? w0 : (which == 1) ? w1 : w2;
    int8_t*     dst = (which == 0) ? d0 : (which == 1) ? d1 : d2;

    const long long i = ((long long)blockIdx.x * blockDim.x + threadIdx.x) * 16;
    if (i >= WELEMS) return;

    if (g_is32[which]) {
        const int4* s = (const int4*)src + (i >> 2);
        char pk[16];
        #pragma unroll
        for (int q = 0; q < 4; q++) {
            const int4 v = s[q];
            pk[q * 4 + 0] = (signed char)v.x;
            pk[q * 4 + 1] = (signed char)v.y;
            pk[q * 4 + 2] = (signed char)v.z;
            pk[q * 4 + 3] = (signed char)v.w;
        }
        *(int4*)(dst + i) = *(const int4*)pk;
    } else {
        *(int4*)(dst + i) = *((const int4*)src + (i >> 4));
    }
}

// ---------------------------------------------------------------------------
// Kernel 0: per-token dynamic int8 quantization of x
// ---------------------------------------------------------------------------
__global__ __launch_bounds__(256) void quant_x_kernel(const float* __restrict__ x) {
    const int row = blockIdx.x;
    const float4* xr = (const float4*)(x + (size_t)row * HDIM);
    const int nv = HDIM / 4;

    float m = 0.0f;
    for (int i = threadIdx.x; i < nv; i += blockDim.x) {
        float4 v = xr[i];
        m = fmaxf(m, fmaxf(fmaxf(fabsf(v.x), fabsf(v.y)), fmaxf(fabsf(v.z), fabsf(v.w))));
    }
    __shared__ float red[32];
    #pragma unroll
    for (int o = 16; o; o >>= 1) m = fmaxf(m, __shfl_xor_sync(0xFFFFFFFFu, m, o));
    if ((threadIdx.x & 31) == 0) red[threadIdx.x >> 5] = m;
    __syncthreads();
    if (threadIdx.x < 32) {
        float v = (threadIdx.x < (blockDim.x >> 5)) ? red[threadIdx.x] : 0.0f;
        #pragma unroll
        for (int o = 16; o; o >>= 1) v = fmaxf(v, __shfl_xor_sync(0xFFFFFFFFu, v, o));
        if (threadIdx.x == 0) red[0] = v;
    }
    __syncthreads();
    const float s = fmaxf(red[0] / 127.0f, 1e-8f);
    if (threadIdx.x == 0) g_sx[row] = s;

    char4* qr = (char4*)(g_qx + (size_t)row * HDIM);
    for (int i = threadIdx.x; i < nv; i += blockDim.x) {
        float4 v = xr[i];
        char4 q;
        q.x = (signed char)(int)fminf(fmaxf(rintf(v.x / s), -127.0f), 127.0f);
        q.y = (signed char)(int)fminf(fmaxf(rintf(v.y / s), -127.0f), 127.0f);
        q.z = (signed char)(int)fminf(fmaxf(rintf(v.z / s), -127.0f), 127.0f);
        q.w = (signed char)(int)fminf(fmaxf(rintf(v.w / s), -127.0f), 127.0f);
        qr[i] = q;
    }
}

// ---------------------------------------------------------------------------
// fc1 HYBRID (R9 exact): 512 threads, BM=128, BN=128, BK=128, 3-stage ring.
//   warps 0-7 : IMMA on cols [n0, n0+64)
//   warps 8-15: dp4a on cols [n0+64, n0+128)
// ---------------------------------------------------------------------------
__global__ __launch_bounds__(512, 1) void fc1_kernel(
    const float* __restrict__ gsp, const float* __restrict__ usp,
    const float* __restrict__ disp)
{
    extern __shared__ __align__(128) int8_t smem[];
    const uint32_t sb = smem_u32(smem);

    const int tid = threadIdx.x;
    const int m0 = blockIdx.x * 128;   // M fastest -> weight L2 reuse
    const int n0 = blockIdx.y * 128;

    auto load_stage = [&](int s) {
        const uint32_t base = sb + (uint32_t)(s % 3) * FC1_STG;
        const int kb = s * 128;
        #pragma unroll
        for (int i = 0; i < 2; i++) {
            const int idx = tid + i * 512;
            const int r = idx >> 3, c = (idx & 7) * 16;
            cp16(base + r * SSTR + c,         g_qx  + (size_t)(m0 + r) * HDIM + kb + c);
            cp16(base + 18432 + r * SSTR + c, g_w8g + (size_t)(n0 + r) * HDIM + kb + c);
            cp16(base + 36864 + r * SSTR + c, g_w8u + (size_t)(n0 + r) * HDIM + kb + c);
        }
    };

    const int S = HDIM / 128;  // 28
    load_stage(0); cp_commit();
    load_stage(1); cp_commit();

    if (tid < 256) {
        // ===================== IMMA half (warps 0-7) =====================
        const int warp = tid >> 5, lane = tid & 31;
        const int wm = warp >> 1, wn = warp & 1;
        const int g  = lane >> 2, tg = lane & 3;
        const uint32_t aoff = (uint32_t)(((lane & 7) + ((lane >> 3) & 1) * 8) * SSTR + (lane >> 4) * 16);
        const uint32_t boff = (uint32_t)(((lane & 7) + (lane >> 4) * 8) * SSTR + ((lane >> 3) & 1) * 16);

        int accG[2][4][4] = {};
        int accU[2][4][4] = {};

        for (int s = 0; s < S; s++) {
            cp_wait<1>();
            __syncthreads();
            if (s + 2 < S) load_stage(s + 2);
            cp_commit();

            const uint32_t base = sb + (uint32_t)(s % 3) * FC1_STG;
            const uint32_t abase = base + (uint32_t)(wm * 32) * SSTR + aoff;
            const uint32_t gbase = base + 18432 + (uint32_t)(wn * 32) * SSTR + boff;
            const uint32_t ubase = base + 36864 + (uint32_t)(wn * 32) * SSTR + boff;

            #pragma unroll
            for (int ks = 0; ks < 4; ks++) {
                uint32_t a[2][4];
                ldsm_x4(a[0], abase + ks * 32);
                ldsm_x4(a[1], abase + 16 * SSTR + ks * 32);
                #pragma unroll
                for (int p = 0; p < 2; p++) {
                    uint32_t bg[4], bu[4];
                    ldsm_x4(bg, gbase + p * 16 * SSTR + ks * 32);
                    ldsm_x4(bu, ubase + p * 16 * SSTR + ks * 32);
                    #pragma unroll
                    for (int mt = 0; mt < 2; mt++) {
                        mma_s8(accG[mt][2 * p],     a[mt], bg[0], bg[1]);
                        mma_s8(accG[mt][2 * p + 1], a[mt], bg[2], bg[3]);
                        mma_s8(accU[mt][2 * p],     a[mt], bu[0], bu[1]);
                        mma_s8(accU[mt][2 * p + 1], a[mt], bu[2], bu[3]);
                    }
                }
            }
        }

        const float gscale = *gsp, uscale = *usp, dis = *disp;
        #pragma unroll
        for (int mt = 0; mt < 2; mt++) {
            const int r0 = m0 + wm * 32 + mt * 16 + g;
            const float s0 = g_sx[r0], s1 = g_sx[r0 + 8];
            #pragma unroll
            for (int nt = 0; nt < 4; nt++) {
                const int c = n0 + wn * 32 + nt * 8 + tg * 2;
                char2 v0, v1;
                v0.x = qsilu(accG[mt][nt][0], accU[mt][nt][0], s0, gscale, uscale, dis);
                v0.y = qsilu(accG[mt][nt][1], accU[mt][nt][1], s0, gscale, uscale, dis);
                v1.x = qsilu(accG[mt][nt][2], accU[mt][nt][2], s1, gscale, uscale, dis);
                v1.y = qsilu(accG[mt][nt][3], accU[mt][nt][3], s1, gscale, uscale, dis);
                *(char2*)&g_qh[(size_t)r0 * IDIM + c]       = v0;
                *(char2*)&g_qh[(size_t)(r0 + 8) * IDIM + c] = v1;
            }
        }
    } else {
        // ===================== dp4a half (warps 8-15) =====================
        const int wt = tid - 256;
        const int ty = wt >> 4, tx = wt & 15;

        int ag[8][4] = {};
        int au[8][4] = {};

        for (int s = 0; s < S; s++) {
            cp_wait<1>();
            __syncthreads();
            if (s + 2 < S) load_stage(s + 2);
            cp_commit();

            const int so = (s % 3) * FC1_STG;
            const int8_t* Ab = smem + so + ty * 8 * SSTR;
            const int8_t* Gb = smem + so + 18432 + (64 + tx) * SSTR;
            const int8_t* Ub = smem + so + 36864 + (64 + tx) * SSTR;

            #pragma unroll
            for (int k4 = 0; k4 < 8; k4++) {
                int4 a4[8];
                #pragma unroll
                for (int i = 0; i < 8; i++)
                    a4[i] = *(const int4*)(Ab + i * SSTR + k4 * 16);
                #pragma unroll
                for (int j = 0; j < 4; j++) {
                    const int4 bg4 = *(const int4*)(Gb + j * 16 * SSTR + k4 * 16);
                    const int4 bu4 = *(const int4*)(Ub + j * 16 * SSTR + k4 * 16);
                    #pragma unroll
                    for (int i = 0; i < 8; i++) {
                        dp4x4(ag[i][j], a4[i], bg4);
                        dp4x4(au[i][j], a4[i], bu4);
                    }
                }
            }
        }

        const float gscale = *gsp, uscale = *usp, dis = *disp;
        #pragma unroll
        for (int i = 0; i < 8; i++) {
            const int row = m0 + ty * 8 + i;
            const float srow = g_sx[row];
            #pragma unroll
            for (int j = 0; j < 4; j++) {
                const int col = n0 + 64 + tx + 16 * j;
                g_qh[(size_t)row * IDIM + col] =
                    qsilu(ag[i][j], au[i][j], srow, gscale, uscale, dis);
            }
        }
    }
}

// ---------------------------------------------------------------------------
// fc2 HYBRID (R9 exact): 512 threads, BM=128, BN=128, BK=128, 3-stage ring.
// ---------------------------------------------------------------------------
__global__ __launch_bounds__(512, 1) void fc2_kernel(
    const float* __restrict__ dsp, const float* __restrict__ disp,
    float* __restrict__ out)
{
    extern __shared__ __align__(128) int8_t smem[];
    const uint32_t sb = smem_u32(smem);

    const int tid = threadIdx.x;
    const int m0 = blockIdx.x * 128;
    const int n0 = blockIdx.y * 128;

    auto load_stage = [&](int s) {
        const uint32_t base = sb + (uint32_t)(s % 3) * FC2_STG;
        const int kb = s * 128;
        #pragma unroll
        for (int i = 0; i < 2; i++) {
            const int idx = tid + i * 512;
            const int r = idx >> 3, c = (idx & 7) * 16;
            cp16(base + r * SSTR + c,         g_qh  + (size_t)(m0 + r) * IDIM + kb + c);
            cp16(base + 18432 + r * SSTR + c, g_w8d + (size_t)(n0 + r) * IDIM + kb + c);
        }
    };

    const int S = IDIM / 128;  // 148
    load_stage(0); cp_commit();
    load_stage(1); cp_commit();

    if (tid < 256) {
        // ===================== IMMA half =====================
        const int warp = tid >> 5, lane = tid & 31;
        const int wm = warp >> 1, wn = warp & 1;
        const int g  = lane >> 2, tg = lane & 3;
        const uint32_t aoff = (uint32_t)(((lane & 7) + ((lane >> 3) & 1) * 8) * SSTR + (lane >> 4) * 16);
        const uint32_t boff = (uint32_t)(((lane & 7) + (lane >> 4) * 8) * SSTR + ((lane >> 3) & 1) * 16);

        int acc[2][4][4] = {};

        for (int s = 0; s < S; s++) {
            cp_wait<1>();
            __syncthreads();
            if (s + 2 < S) load_stage(s + 2);
            cp_commit();

            const uint32_t base = sb + (uint32_t)(s % 3) * FC2_STG;
            const uint32_t abase = base + (uint32_t)(wm * 32) * SSTR + aoff;
            const uint32_t bbase = base + 18432 + (uint32_t)(wn * 32) * SSTR + boff;

            #pragma unroll
            for (int ks = 0; ks < 4; ks++) {
                uint32_t a[2][4];
                ldsm_x4(a[0], abase + ks * 32);
                ldsm_x4(a[1], abase + 16 * SSTR + ks * 32);
                #pragma unroll
                for (int p = 0; p < 2; p++) {
                    uint32_t bb[4];
                    ldsm_x4(bb, bbase + p * 16 * SSTR + ks * 32);
                    #pragma unroll
                    for (int mt = 0; mt < 2; mt++) {
                        mma_s8(acc[mt][2 * p],     a[mt], bb[0], bb[1]);
                        mma_s8(acc[mt][2 * p + 1], a[mt], bb[2], bb[3]);
                    }
                }
            }
        }

        const float oscale = (*disp) * (*dsp);
        #pragma unroll
        for (int mt = 0; mt < 2; mt++) {
            const int r0 = m0 + wm * 32 + mt * 16 + g;
            #pragma unroll
            for (int nt = 0; nt < 4; nt++) {
                const int c = n0 + wn * 32 + nt * 8 + tg * 2;
                float2 v0, v1;
                v0.x = (float)acc[mt][nt][0] * oscale;
                v0.y = (float)acc[mt][nt][1] * oscale;
                v1.x = (float)acc[mt][nt][2] * oscale;
                v1.y = (float)acc[mt][nt][3] * oscale;
                *(float2*)&out[(size_t)r0 * HDIM + c]       = v0;
                *(float2*)&out[(size_t)(r0 + 8) * HDIM + c] = v1;
            }
        }
    } else {
        // ===================== dp4a half =====================
        const int wt = tid - 256;
        const int ty = wt >> 4, tx = wt & 15;

        int acc[8][4] = {};

        for (int s = 0; s < S; s++) {
            cp_wait<1>();
            __syncthreads();
            if (s + 2 < S) load_stage(s + 2);
            cp_commit();

            const int so = (s % 3) * FC2_STG;
            const int8_t* Ab = smem + so + ty * 8 * SSTR;
            const int8_t* Bb = smem + so + 18432 + (64 + tx) * SSTR;

            #pragma unroll
            for (int k4 = 0; k4 < 8; k4++) {
                int4 a4[8];
                #pragma unroll
                for (int i = 0; i < 8; i++)
                    a4[i] = *(const int4*)(Ab + i * SSTR + k4 * 16);
                #pragma unroll
                for (int j = 0; j < 4; j++) {
                    const int4 b4 = *(const int4*)(Bb + j * 16 * SSTR + k4 * 16);
                    #pragma unroll
                    for (int i = 0; i < 8; i++)
                        dp4x4(acc[i][j], a4[i], b4);
                }
            }
        }

        const float oscale = (*disp) * (*dsp);
        #pragma unroll
        for (int i = 0; i < 8; i++) {
            const int row = m0 + ty * 8 + i;
            #pragma unroll
            for (int j = 0; j < 4; j++) {
                const int col = n0 + 64 + tx + 16 * j;
                out[(size_t)row * HDIM + col] = (float)acc[i][j] * oscale;
            }
        }
    }
}

// ---------------------------------------------------------------------------
// Entry point
// ---------------------------------------------------------------------------
extern "C" void kernel_launch(void* const* d_in, const int* in_sizes, int n_in,
                              void* d_out, int out_size) {
    const int XSZ = T_TOKENS * HDIM;

    int xi = -1, widx[3] = {-1,-1,-1}, sidx[4] = {-1,-1,-1,-1};
    int nw = 0, ns = 0;
    for (int i = 0; i < n_in; i++) {
        if (in_sizes[i] == XSZ) xi = i;
        else if ((long long)in_sizes[i] == WELEMS) { if (nw < 3) widx[nw++] = i; }
        else if (in_sizes[i] == 1) { if (ns < 4) sidx[ns++] = i; }
    }

    const float *x, *gs, *us, *ds, *dis;
    const void *gw, *uw, *dw;

    if (xi == 0) {
        x   = (const float*)d_in[xi];
        gw  = d_in[widx[0]];
        uw  = d_in[widx[1]];
        dw  = d_in[widx[2]];
        gs  = (const float*)d_in[sidx[0]];
        us  = (const float*)d_in[sidx[1]];
        ds  = (const float*)d_in[sidx[2]];
        dis = (const float*)d_in[sidx[3]];
    } else {
        x   = (const float*)d_in[xi];
        dw  = d_in[widx[0]];
        gw  = d_in[widx[1]];
        uw  = d_in[widx[2]];
        dis = (const float*)d_in[sidx[0]];
        ds  = (const float*)d_in[sidx[1]];
        gs  = (const float*)d_in[sidx[2]];
        us  = (const float*)d_in[sidx[3]];
    }

    float* out = (float*)d_out;

    static int smem_set = 0;
    if (!smem_set) {
        cudaFuncSetAttribute(fc1_kernel, cudaFuncAttributeMaxDynamicSharedMemorySize, FC1_SMEM);
        cudaFuncSetAttribute(fc2_kernel, cudaFuncAttributeMaxDynamicSharedMemorySize, FC2_SMEM);
        smem_set = 1;
    }

    detect_kernel<<<1, 32>>>(gw, uw, dw);

    int8_t* w8g; cudaGetSymbolAddress((void**)&w8g, g_w8g);
    int8_t* w8u; cudaGetSymbolAddress((void**)&w8u, g_w8u);
    int8_t* w8d; cudaGetSymbolAddress((void**)&w8d, g_w8d);
    const int rp_blocks = (int)((WELEMS / 16 + 255) / 256);
    repack_all_kernel<<<dim3(rp_blocks, 3), 256>>>(gw, uw, dw, w8g, w8u, w8d);

    quant_x_kernel<<<T_TOKENS, 256>>>(x);

    // M fastest (grid.x) so concurrent CTAs share weight stripes in L2.
    fc1_kernel<<<dim3(T_TOKENS / 128, IDIM / 128), 512, FC1_SMEM>>>(gs, us, dis);
    fc2_kernel<<<dim3(T_TOKENS / 128, HDIM / 128), 512, FC2_SMEM>>>(ds, dis, out);
}